// round 5
// baseline (speedup 1.0000x reference)
#include <cuda_runtime.h>
#include <cuda_bf16.h>
#include <cstdint>
#include <math.h>

#define B_SZ 8192
#define D_SZ 256
#define INV_T (1.0f / 0.07f)

// ---------------- scratch (no allocations allowed) ----------------
__device__ __align__(16) int8_t g_q8[B_SZ * D_SZ];   // 2 MB
__device__ __align__(16) int8_t g_t8[B_SZ * D_SZ];   // 2 MB
__device__ float g_sq[B_SZ];       // per-row q scale
__device__ float g_st[B_SZ];       // per-row t scale
__device__ float g_pos[B_SZ];
__device__ float g_ps[2 * B_SZ];   // per-colsplit row sum of exp

// ---------------- kernel 1: normalize + int8 quantize ----------------
__global__ __launch_bounds__(256) void norm_kernel(const float* __restrict__ h,
                                                   const float* __restrict__ r,
                                                   const float* __restrict__ t) {
    int wid = threadIdx.x >> 5;
    int lane = threadIdx.x & 31;
    int row = blockIdx.x * 8 + wid;

    const float4* h4 = (const float4*)h;
    const float4* r4 = (const float4*)r;
    const float4* t4 = (const float4*)t;
    int base = row * 64;

    float4 ha = h4[base + lane];
    float4 hb = h4[base + 32 + lane];
    float4 ra = r4[base + lane];
    float4 rb = r4[base + 32 + lane];
    float4 va = make_float4(ha.x + ra.x, ha.y + ra.y, ha.z + ra.z, ha.w + ra.w);
    float4 vb = make_float4(hb.x + rb.x, hb.y + rb.y, hb.z + rb.z, hb.w + rb.w);

    float ss = va.x * va.x + va.y * va.y + va.z * va.z + va.w * va.w +
               vb.x * vb.x + vb.y * vb.y + vb.z * vb.z + vb.w * vb.w;
#pragma unroll
    for (int o = 16; o > 0; o >>= 1) ss += __shfl_xor_sync(0xffffffffu, ss, o);
    float qinv = rsqrtf(fmaxf(ss, 1e-24f));

    float4 ta = t4[base + lane];
    float4 tb = t4[base + 32 + lane];
    float ts = ta.x * ta.x + ta.y * ta.y + ta.z * ta.z + ta.w * ta.w +
               tb.x * tb.x + tb.y * tb.y + tb.z * tb.z + tb.w * tb.w;
#pragma unroll
    for (int o = 16; o > 0; o >>= 1) ts += __shfl_xor_sync(0xffffffffu, ts, o);
    float tinv = rsqrtf(fmaxf(ts, 1e-24f));

    float qa0 = va.x * qinv, qa1 = va.y * qinv, qa2 = va.z * qinv, qa3 = va.w * qinv;
    float qb0 = vb.x * qinv, qb1 = vb.y * qinv, qb2 = vb.z * qinv, qb3 = vb.w * qinv;
    float ta0 = ta.x * tinv, ta1 = ta.y * tinv, ta2 = ta.z * tinv, ta3 = ta.w * tinv;
    float tb0 = tb.x * tinv, tb1 = tb.y * tinv, tb2 = tb.z * tinv, tb3 = tb.w * tinv;

    // row max(|.|) for q and t
    float qm = fmaxf(fmaxf(fmaxf(fabsf(qa0), fabsf(qa1)), fmaxf(fabsf(qa2), fabsf(qa3))),
                     fmaxf(fmaxf(fabsf(qb0), fabsf(qb1)), fmaxf(fabsf(qb2), fabsf(qb3))));
    float tm = fmaxf(fmaxf(fmaxf(fabsf(ta0), fabsf(ta1)), fmaxf(fabsf(ta2), fabsf(ta3))),
                     fmaxf(fmaxf(fabsf(tb0), fabsf(tb1)), fmaxf(fabsf(tb2), fabsf(tb3))));
#pragma unroll
    for (int o = 16; o > 0; o >>= 1) {
        qm = fmaxf(qm, __shfl_xor_sync(0xffffffffu, qm, o));
        tm = fmaxf(tm, __shfl_xor_sync(0xffffffffu, tm, o));
    }
    float qscale = qm * (1.0f / 127.0f);
    float tscale = tm * (1.0f / 127.0f);
    float qrs = (qm > 0.f) ? 127.0f / qm : 0.f;
    float trs = (tm > 0.f) ? 127.0f / tm : 0.f;

    // quantize + pack 4 x int8 -> u32
    uint32_t* q32 = (uint32_t*)(g_q8 + row * D_SZ);
    uint32_t* t32 = (uint32_t*)(g_t8 + row * D_SZ);
#define PACK4(x0, x1, x2, x3, sc)                                            \
    ((uint32_t)(__float2int_rn((x0) * (sc)) & 0xff) |                        \
     ((uint32_t)(__float2int_rn((x1) * (sc)) & 0xff) << 8) |                 \
     ((uint32_t)(__float2int_rn((x2) * (sc)) & 0xff) << 16) |                \
     ((uint32_t)(__float2int_rn((x3) * (sc)) & 0xff) << 24))
    q32[lane]      = PACK4(qa0, qa1, qa2, qa3, qrs);
    q32[32 + lane] = PACK4(qb0, qb1, qb2, qb3, qrs);
    t32[lane]      = PACK4(ta0, ta1, ta2, ta3, trs);
    t32[32 + lane] = PACK4(tb0, tb1, tb2, tb3, trs);
#undef PACK4

    // exact fp32 positive similarity
    float p = qa0 * ta0 + qa1 * ta1 + qa2 * ta2 + qa3 * ta3 +
              qb0 * tb0 + qb1 * tb1 + qb2 * tb2 + qb3 * tb3;
#pragma unroll
    for (int o = 16; o > 0; o >>= 1) p += __shfl_xor_sync(0xffffffffu, p, o);
    if (lane == 0) {
        g_pos[row] = p * INV_T;
        g_sq[row] = qscale;
        g_st[row] = tscale;
    }
}

// ---------------- kernel 2: IMMA GEMM + fused exp-sum ----------------
// grid (64 row-tiles, 2 col-splits), 256 threads (8 warps, 4 rows x 2 cols).
// q tile 128x256 int8 resident; 32 t chunks (128x256 int8) cp.async dbl-buffered.
#define NCH 32
#define SQB 272                              // bytes per smem tile row (256+16)
#define TBYTES (128 * SQB)                   // 34816 B per tile
#define QOFF 0
#define T0OFF TBYTES
#define T1OFF (2 * TBYTES)
#define STOFF (3 * TBYTES)                   // two 512B st buffers
#define SMEM_TOTAL (STOFF + 1024)

__device__ __forceinline__ void cp16(uint32_t dst, const void* src) {
    asm volatile("cp.async.cg.shared.global [%0], [%1], 16;\n" :: "r"(dst), "l"(src));
}
__device__ __forceinline__ void cp4(uint32_t dst, const void* src) {
    asm volatile("cp.async.ca.shared.global [%0], [%1], 4;\n" :: "r"(dst), "l"(src));
}
__device__ __forceinline__ void cp_commit() {
    asm volatile("cp.async.commit_group;\n" ::: "memory");
}
template <int N>
__device__ __forceinline__ void cp_wait() {
    asm volatile("cp.async.wait_group %0;\n" :: "n"(N) : "memory");
}

__device__ __forceinline__ void mma_s8(int c[4], const uint32_t a[4], const uint32_t* b) {
    asm volatile(
        "mma.sync.aligned.m16n8k32.row.col.s32.s8.s8.s32 "
        "{%0,%1,%2,%3}, {%4,%5,%6,%7}, {%8,%9}, {%0,%1,%2,%3};\n"
        : "+r"(c[0]), "+r"(c[1]), "+r"(c[2]), "+r"(c[3])
        : "r"(a[0]), "r"(a[1]), "r"(a[2]), "r"(a[3]), "r"(b[0]), "r"(b[1]));
}

__global__ __launch_bounds__(256, 1) void gemm_lse_kernel() {
    extern __shared__ char smem[];
    const uint32_t sbase = (uint32_t)__cvta_generic_to_shared(smem);

    const int tid = threadIdx.x;
    const int wid = tid >> 5;
    const int lane = tid & 31;
    const int row0 = blockIdx.x * 128;
    const int csplit = blockIdx.y;
    const int col_base = csplit * 4096;

    // ---- initial loads: q tile + t0 + st0 (group 0), t1 + st1 (group 1) ----
    {
        const int8_t* qsrc = g_q8 + (size_t)row0 * D_SZ;
        const int8_t* tsrc = g_t8 + (size_t)col_base * D_SZ;
        for (int i = tid; i < 128 * 16; i += 256) {
            int rr = i >> 4;
            int cb16 = (i & 15) * 16;
            cp16(sbase + QOFF + rr * SQB + cb16, qsrc + rr * D_SZ + cb16);
            cp16(sbase + T0OFF + rr * SQB + cb16, tsrc + rr * D_SZ + cb16);
        }
        if (tid < 128) cp4(sbase + STOFF + tid * 4, g_st + col_base + tid);
        cp_commit();
        const int8_t* tsrc1 = g_t8 + (size_t)(col_base + 128) * D_SZ;
        for (int i = tid; i < 128 * 16; i += 256) {
            int rr = i >> 4;
            int cb16 = (i & 15) * 16;
            cp16(sbase + T1OFF + rr * SQB + cb16, tsrc1 + rr * D_SZ + cb16);
        }
        if (tid < 128) cp4(sbase + STOFF + 512 + tid * 4, g_st + col_base + 128 + tid);
        cp_commit();
    }

    // warp tile: 32 rows x 64 cols; warps 4 (rows) x 2 (cols)
    const int wr = (wid >> 1) * 32;
    const int wc = (wid & 1) * 64;

    // per-thread row scales (folded with 1/T): rows wr + mt*16 + (lane>>2) + {0,8}
    float fr[4];
#pragma unroll
    for (int i = 0; i < 4; i++) {
        int rrow = wr + (i >> 1) * 16 + (i & 1) * 8 + (lane >> 2);
        fr[i] = g_sq[row0 + rrow] * INV_T;
    }

    // A ldmatrix addresses (x4: 16 rows x two 16B k-halves)
    uint32_t aAddr[2];
#pragma unroll
    for (int mt = 0; mt < 2; mt++) {
        int rrow = wr + mt * 16 + (lane & 15);
        aAddr[mt] = sbase + QOFF + rrow * SQB + (lane >> 4) * 16;
    }
    // B ldmatrix addresses (x4: 2 n8 frags x 2 k-halves) per buffer
    uint32_t bAddr[2][4];
#pragma unroll
    for (int p = 0; p < 4; p++) {
        int nt = 2 * p + (lane >> 4);
        int khalf = (lane >> 3) & 1;
        int rrow = wc + nt * 8 + (lane & 7);
        uint32_t off = (uint32_t)(rrow * SQB + khalf * 16);
        bAddr[0][p] = sbase + T0OFF + off;
        bAddr[1][p] = sbase + T1OFF + off;
    }

    float rsum[4] = {0.f, 0.f, 0.f, 0.f};

    for (int ci = 0; ci < NCH; ci++) {
        if (ci == NCH - 1) cp_wait<0>(); else cp_wait<1>();
        __syncthreads();

        const int cb = ci & 1;
        int acc[2][8][4];
#pragma unroll
        for (int mt = 0; mt < 2; mt++)
#pragma unroll
            for (int nt = 0; nt < 8; nt++)
#pragma unroll
                for (int k = 0; k < 4; k++) acc[mt][nt][k] = 0;

#pragma unroll
        for (int ks = 0; ks < 8; ks++) {
            uint32_t a[2][4];
            uint32_t b[8][2];
#pragma unroll
            for (int mt = 0; mt < 2; mt++) {
                asm volatile(
                    "ldmatrix.sync.aligned.m8n8.x4.shared.b16 {%0,%1,%2,%3}, [%4];\n"
                    : "=r"(a[mt][0]), "=r"(a[mt][1]), "=r"(a[mt][2]), "=r"(a[mt][3])
                    : "r"(aAddr[mt] + ks * 32));
            }
#pragma unroll
            for (int p = 0; p < 4; p++) {
                asm volatile(
                    "ldmatrix.sync.aligned.m8n8.x4.shared.b16 {%0,%1,%2,%3}, [%4];\n"
                    : "=r"(b[2 * p][0]), "=r"(b[2 * p][1]),
                      "=r"(b[2 * p + 1][0]), "=r"(b[2 * p + 1][1])
                    : "r"(bAddr[cb][p] + ks * 32));
            }
#pragma unroll
            for (int mt = 0; mt < 2; mt++)
#pragma unroll
                for (int nt = 0; nt < 8; nt++) mma_s8(acc[mt][nt], a[mt], b[nt]);
        }

        // fused epilogue: scale -> exp -> per-thread row partials
        {
            const float* stb = (const float*)(smem + STOFF + cb * 512);
#pragma unroll
            for (int mt = 0; mt < 2; mt++) {
                float s0 = 0.f, s1 = 0.f;
#pragma unroll
                for (int nt = 0; nt < 8; nt++) {
                    int c0 = wc + nt * 8 + (lane & 3) * 2;
                    float st0 = stb[c0], st1 = stb[c0 + 1];
                    s0 += __expf((float)acc[mt][nt][0] * fr[mt * 2] * st0) +
                          __expf((float)acc[mt][nt][1] * fr[mt * 2] * st1);
                    s1 += __expf((float)acc[mt][nt][2] * fr[mt * 2 + 1] * st0) +
                          __expf((float)acc[mt][nt][3] * fr[mt * 2 + 1] * st1);
                }
                rsum[mt * 2]     += s0;
                rsum[mt * 2 + 1] += s1;
            }
        }

        __syncthreads();
        // refill this buffer with chunk ci+2
        if (ci + 2 < NCH) {
            const int8_t* tsrc = g_t8 + (size_t)(col_base + (ci + 2) * 128) * D_SZ;
            uint32_t tb = sbase + (cb ? T1OFF : T0OFF);
            for (int i = tid; i < 128 * 16; i += 256) {
                int rr = i >> 4;
                int cb16 = (i & 15) * 16;
                cp16(tb + rr * SQB + cb16, tsrc + rr * D_SZ + cb16);
            }
            if (tid < 128)
                cp4(sbase + STOFF + cb * 512 + tid * 4, g_st + col_base + (ci + 2) * 128 + tid);
            cp_commit();
        }
    }

    // ---- cross-lane (same row) then cross-warp (col halves) reduction ----
#pragma unroll
    for (int i = 0; i < 4; i++) {
        float v = rsum[i];
        v += __shfl_xor_sync(0xffffffffu, v, 1);
        v += __shfl_xor_sync(0xffffffffu, v, 2);
        rsum[i] = v;
    }
    __syncthreads();
    float* red = (float*)smem;   // 128 rows x 2 col-halves
    if ((lane & 3) == 0) {
        int g = lane >> 2;
#pragma unroll
        for (int i = 0; i < 4; i++) {
            int rrow = wr + (i >> 1) * 16 + (i & 1) * 8 + g;
            red[rrow * 2 + (wid & 1)] = rsum[i];
        }
    }
    __syncthreads();
    if (tid < 128)
        g_ps[csplit * B_SZ + row0 + tid] = red[tid * 2] + red[tid * 2 + 1];
}

// ---------------- kernel 3: combine + mean ----------------
__global__ __launch_bounds__(256) void reduce_kernel(float* __restrict__ out) {
    __shared__ double red[256];
    int tid = threadIdx.x;
    double acc = 0.0;
    for (int rI = tid; rI < B_SZ; rI += 256) {
        float s = g_ps[rI] + g_ps[B_SZ + rI];
        acc += (double)(logf(s) - g_pos[rI]);
    }
    red[tid] = acc;
    __syncthreads();
    for (int o = 128; o > 0; o >>= 1) {
        if (tid < o) red[tid] += red[tid + o];
        __syncthreads();
    }
    if (tid == 0) out[0] = (float)(red[0] / (double)B_SZ);
}

// ---------------- launch ----------------
extern "C" void kernel_launch(void* const* d_in, const int* in_sizes, int n_in,
                              void* d_out, int out_size) {
    const float* h = (const float*)d_in[0];
    const float* r = (const float*)d_in[1];
    const float* t = (const float*)d_in[2];
    float* out = (float*)d_out;

    static bool attr_set = false;
    if (!attr_set) {
        cudaFuncSetAttribute(gemm_lse_kernel, cudaFuncAttributeMaxDynamicSharedMemorySize,
                             SMEM_TOTAL);
        attr_set = true;
    }

    norm_kernel<<<B_SZ / 8, 256>>>(h, r, t);
    gemm_lse_kernel<<<dim3(64, 2), 256, SMEM_TOTAL>>>();
    reduce_kernel<<<1, 256>>>(out);
}

// round 6
// speedup vs baseline: 2.7536x; 2.7536x over previous
#include <cuda_runtime.h>
#include <cuda_bf16.h>
#include <cstdint>
#include <math.h>

#define B_SZ 8192
#define D_SZ 256
#define INV_T (1.0f / 0.07f)
#define KC (1.4426950408889634f / 0.07f)   // log2(e)/T
#define NCTA 148
#define NJOB 4096                           // 64 rowtiles x 64 chunks

// ---------------- scratch (no allocations allowed) ----------------
__device__ __align__(16) __nv_bfloat16 g_q[B_SZ * D_SZ];   // 4 MB
__device__ __align__(16) __nv_bfloat16 g_t[B_SZ * D_SZ];   // 4 MB
__device__ float g_pos[B_SZ];
__device__ float g_part[NJOB * 256];        // per job: 2 col-halves x 128 rows (4 MB)
__device__ double g_bred[32];

// ---------------- kernel 1: normalize ----------------
__global__ __launch_bounds__(256) void norm_kernel(const float* __restrict__ h,
                                                   const float* __restrict__ r,
                                                   const float* __restrict__ t) {
    int wid = threadIdx.x >> 5;
    int lane = threadIdx.x & 31;
    int row = blockIdx.x * 8 + wid;

    const float4* h4 = (const float4*)h;
    const float4* r4 = (const float4*)r;
    const float4* t4 = (const float4*)t;
    int base = row * 64;

    float4 ha = h4[base + lane];
    float4 hb = h4[base + 32 + lane];
    float4 ra = r4[base + lane];
    float4 rb = r4[base + 32 + lane];
    float4 va = make_float4(ha.x + ra.x, ha.y + ra.y, ha.z + ra.z, ha.w + ra.w);
    float4 vb = make_float4(hb.x + rb.x, hb.y + rb.y, hb.z + rb.z, hb.w + rb.w);

    float ss = va.x * va.x + va.y * va.y + va.z * va.z + va.w * va.w +
               vb.x * vb.x + vb.y * vb.y + vb.z * vb.z + vb.w * vb.w;
#pragma unroll
    for (int o = 16; o > 0; o >>= 1) ss += __shfl_xor_sync(0xffffffffu, ss, o);
    float qinv = rsqrtf(fmaxf(ss, 1e-24f));

    float4 ta = t4[base + lane];
    float4 tb = t4[base + 32 + lane];
    float ts = ta.x * ta.x + ta.y * ta.y + ta.z * ta.z + ta.w * ta.w +
               tb.x * tb.x + tb.y * tb.y + tb.z * tb.z + tb.w * tb.w;
#pragma unroll
    for (int o = 16; o > 0; o >>= 1) ts += __shfl_xor_sync(0xffffffffu, ts, o);
    float tinv = rsqrtf(fmaxf(ts, 1e-24f));

    float qa0 = va.x * qinv, qa1 = va.y * qinv, qa2 = va.z * qinv, qa3 = va.w * qinv;
    float qb0 = vb.x * qinv, qb1 = vb.y * qinv, qb2 = vb.z * qinv, qb3 = vb.w * qinv;
    float ta0 = ta.x * tinv, ta1 = ta.y * tinv, ta2 = ta.z * tinv, ta3 = ta.w * tinv;
    float tb0 = tb.x * tinv, tb1 = tb.y * tinv, tb2 = tb.z * tinv, tb3 = tb.w * tinv;

    __nv_bfloat162* q2 = (__nv_bfloat162*)(g_q + row * D_SZ);
    __nv_bfloat162* t2 = (__nv_bfloat162*)(g_t + row * D_SZ);
    int c2 = lane * 2;
    q2[c2]      = __floats2bfloat162_rn(qa0, qa1);
    q2[c2 + 1]  = __floats2bfloat162_rn(qa2, qa3);
    q2[c2 + 64] = __floats2bfloat162_rn(qb0, qb1);
    q2[c2 + 65] = __floats2bfloat162_rn(qb2, qb3);
    t2[c2]      = __floats2bfloat162_rn(ta0, ta1);
    t2[c2 + 1]  = __floats2bfloat162_rn(ta2, ta3);
    t2[c2 + 64] = __floats2bfloat162_rn(tb0, tb1);
    t2[c2 + 65] = __floats2bfloat162_rn(tb2, tb3);

    float p = qa0 * ta0 + qa1 * ta1 + qa2 * ta2 + qa3 * ta3 +
              qb0 * tb0 + qb1 * tb1 + qb2 * tb2 + qb3 * tb3;
#pragma unroll
    for (int o = 16; o > 0; o >>= 1) p += __shfl_xor_sync(0xffffffffu, p, o);
    if (lane == 0) g_pos[row] = p * INV_T;
}

// ---------------- kernel 2: persistent HMMA GEMM + fused exp-sum ----------------
// 148 CTAs, 256 threads. Jobs = (rowtile, chunk) rowtile-major; CTA c owns
// jobs [c*4096/148, (c+1)*4096/148). q tile reloaded on rowtile change (<=1/CTA).
#define SQ 264                               // bf16 elems per smem row (+pad)
#define TBYTES (128 * SQ * 2)                // 67584 B per tile
#define QOFF 0
#define T0OFF TBYTES
#define T1OFF (2 * TBYTES)
#define SMEM_TOTAL (3 * TBYTES)

__device__ __forceinline__ void cp16(uint32_t dst, const void* src) {
    asm volatile("cp.async.cg.shared.global [%0], [%1], 16;\n" :: "r"(dst), "l"(src));
}
__device__ __forceinline__ void cp_commit() {
    asm volatile("cp.async.commit_group;\n" ::: "memory");
}
template <int N>
__device__ __forceinline__ void cp_wait() {
    asm volatile("cp.async.wait_group %0;\n" :: "n"(N) : "memory");
}

__device__ __forceinline__ void mma_bf16(float c[4], const uint32_t a[4], const uint32_t* b) {
    asm volatile(
        "mma.sync.aligned.m16n8k16.row.col.f32.bf16.bf16.f32 "
        "{%0,%1,%2,%3}, {%4,%5,%6,%7}, {%8,%9}, {%0,%1,%2,%3};\n"
        : "+f"(c[0]), "+f"(c[1]), "+f"(c[2]), "+f"(c[3])
        : "r"(a[0]), "r"(a[1]), "r"(a[2]), "r"(a[3]), "r"(b[0]), "r"(b[1]));
}

__global__ __launch_bounds__(256, 1) void gemm_lse_kernel() {
    extern __shared__ char smem[];
    const uint32_t sbase = (uint32_t)__cvta_generic_to_shared(smem);

    const int tid = threadIdx.x;
    const int wid = tid >> 5;
    const int lane = tid & 31;
    const int c = blockIdx.x;

    const int j0 = (c * NJOB) / NCTA;
    const int j1 = ((c + 1) * NJOB) / NCTA;
    const int nj = j1 - j0;

    int cur_rt = j0 >> 6;

    // ---- loaders ----
#define LOADQ(rt)                                                              \
    do {                                                                       \
        const __nv_bfloat16* qsrc = g_q + (size_t)((rt) * 128) * D_SZ;         \
        for (int i = tid; i < 128 * 32; i += 256) {                            \
            int rr = i >> 5;                                                   \
            int c8 = (i & 31) * 8;                                             \
            cp16(sbase + QOFF + (rr * SQ + c8) * 2, qsrc + rr * D_SZ + c8);    \
        }                                                                      \
    } while (0)
#define LOADT(off, ch)                                                         \
    do {                                                                       \
        const __nv_bfloat16* tsrc = g_t + (size_t)((ch) * 128) * D_SZ;         \
        for (int i = tid; i < 128 * 32; i += 256) {                            \
            int rr = i >> 5;                                                   \
            int c8 = (i & 31) * 8;                                             \
            cp16(sbase + (off) + (rr * SQ + c8) * 2, tsrc + rr * D_SZ + c8);   \
        }                                                                      \
    } while (0)

    // prologue: group0 = q + t[j0]; group1 = t[j0+1] (possibly empty)
    LOADQ(cur_rt);
    LOADT(T0OFF, j0 & 63);
    cp_commit();
    if (nj > 1) LOADT(T1OFF, (j0 + 1) & 63);
    cp_commit();

    // warp tile: 32 rows x 64 cols; warps 4 (rows) x 2 (cols)
    const int wr = (wid >> 1) * 32;
    const int wc = (wid & 1) * 64;

    uint32_t aAddr[2];
#pragma unroll
    for (int mt = 0; mt < 2; mt++) {
        int rrow = wr + mt * 16 + (lane & 15);
        aAddr[mt] = sbase + QOFF + (uint32_t)(rrow * SQ + (lane >> 4) * 8) * 2;
    }
    uint32_t bAddr[2][4];
#pragma unroll
    for (int p = 0; p < 4; p++) {
        int nt = 2 * p + (lane >> 4);
        int khalf = (lane >> 3) & 1;
        int rrow = wc + nt * 8 + (lane & 7);
        uint32_t off = (uint32_t)(rrow * SQ + khalf * 8) * 2;
        bAddr[0][p] = sbase + T0OFF + off;
        bAddr[1][p] = sbase + T1OFF + off;
    }

    for (int i = 0; i < nj; i++) {
        const int ji = j0 + i;
        const int rt = ji >> 6;
        const int cb = i & 1;

        if (rt != cur_rt) {
            // rowtile boundary: reload q, drain everything
            LOADQ(rt);
            cp_commit();
            cp_wait<0>();
            cur_rt = rt;
        } else if (i >= nj - 2) {
            cp_wait<0>();
        } else {
            cp_wait<1>();
        }
        __syncthreads();

        float acc[2][8][4];
#pragma unroll
        for (int mt = 0; mt < 2; mt++)
#pragma unroll
            for (int nt = 0; nt < 8; nt++)
#pragma unroll
                for (int k = 0; k < 4; k++) acc[mt][nt][k] = 0.0f;

#pragma unroll
        for (int ks = 0; ks < 16; ks++) {
            uint32_t a[2][4];
            uint32_t b[8][2];
#pragma unroll
            for (int mt = 0; mt < 2; mt++) {
                asm volatile(
                    "ldmatrix.sync.aligned.m8n8.x4.shared.b16 {%0,%1,%2,%3}, [%4];\n"
                    : "=r"(a[mt][0]), "=r"(a[mt][1]), "=r"(a[mt][2]), "=r"(a[mt][3])
                    : "r"(aAddr[mt] + ks * 32));
            }
#pragma unroll
            for (int p = 0; p < 4; p++) {
                asm volatile(
                    "ldmatrix.sync.aligned.m8n8.x4.shared.b16 {%0,%1,%2,%3}, [%4];\n"
                    : "=r"(b[2 * p][0]), "=r"(b[2 * p][1]),
                      "=r"(b[2 * p + 1][0]), "=r"(b[2 * p + 1][1])
                    : "r"(bAddr[cb][p] + ks * 32));
            }
#pragma unroll
            for (int mt = 0; mt < 2; mt++)
#pragma unroll
                for (int nt = 0; nt < 8; nt++) mma_bf16(acc[mt][nt], a[mt], b[nt]);
        }

        // fused epilogue: exp2(acc*KC) -> per-thread row partials -> global
        float s[4];
#pragma unroll
        for (int mt = 0; mt < 2; mt++) {
            float s0 = 0.f, s1 = 0.f;
#pragma unroll
            for (int nt = 0; nt < 8; nt++) {
                s0 += exp2f(acc[mt][nt][0] * KC) + exp2f(acc[mt][nt][1] * KC);
                s1 += exp2f(acc[mt][nt][2] * KC) + exp2f(acc[mt][nt][3] * KC);
            }
            s[mt * 2] = s0;
            s[mt * 2 + 1] = s1;
        }
#pragma unroll
        for (int k = 0; k < 4; k++) {
            float v = s[k];
            v += __shfl_xor_sync(0xffffffffu, v, 1);
            v += __shfl_xor_sync(0xffffffffu, v, 2);
            s[k] = v;
        }
        if ((lane & 3) == 0) {
            int g = lane >> 2;
            float* dst = g_part + (size_t)ji * 256 + (wid & 1) * 128 + wr + g;
            dst[0] = s[0];
            dst[8] = s[1];
            dst[16] = s[2];
            dst[24] = s[3];
        }

        __syncthreads();
        // prefetch t for job i+2 into buffer cb
        if (i + 2 < nj) LOADT(cb ? T1OFF : T0OFF, (ji + 2) & 63);
        cp_commit();
    }
#undef LOADQ
#undef LOADT
}

// ---------------- kernel 3a: per-row lse - pos, 32-block partials ----------------
__global__ __launch_bounds__(256) void reduce1_kernel() {
    __shared__ double red[256];
    int tid = threadIdx.x;
    int row = blockIdx.x * 256 + tid;
    int rt = row >> 7, rr = row & 127;
    const float* base = g_part + (size_t)(rt * 64) * 256 + rr;
    float sum = 0.f;
#pragma unroll 8
    for (int ch = 0; ch < 64; ch++) sum += base[ch * 256] + base[ch * 256 + 128];
    red[tid] = (double)(logf(sum) - g_pos[row]);
    __syncthreads();
    for (int o = 128; o > 0; o >>= 1) {
        if (tid < o) red[tid] += red[tid + o];
        __syncthreads();
    }
    if (tid == 0) g_bred[blockIdx.x] = red[0];
}

// ---------------- kernel 3b: final combine ----------------
__global__ void reduce2_kernel(float* __restrict__ out) {
    int tid = threadIdx.x;  // 32 threads
    double v = g_bred[tid];
#pragma unroll
    for (int o = 16; o > 0; o >>= 1) v += __shfl_xor_sync(0xffffffffu, v, o);
    if (tid == 0) out[0] = (float)(v / (double)B_SZ);
}

// ---------------- launch ----------------
extern "C" void kernel_launch(void* const* d_in, const int* in_sizes, int n_in,
                              void* d_out, int out_size) {
    const float* h = (const float*)d_in[0];
    const float* r = (const float*)d_in[1];
    const float* t = (const float*)d_in[2];
    float* out = (float*)d_out;

    static bool attr_set = false;
    if (!attr_set) {
        cudaFuncSetAttribute(gemm_lse_kernel, cudaFuncAttributeMaxDynamicSharedMemorySize,
                             SMEM_TOTAL);
        attr_set = true;
    }

    norm_kernel<<<B_SZ / 8, 256>>>(h, r, t);
    gemm_lse_kernel<<<NCTA, 256, SMEM_TOTAL>>>();
    reduce1_kernel<<<32, 256>>>();
    reduce2_kernel<<<1, 32>>>(out);
}